// round 4
// baseline (speedup 1.0000x reference)
#include <cuda_runtime.h>
#include <cuda_fp16.h>
#include <math.h>
#include <stdint.h>

#define Nn 20000
#define Ee 320000
#define Ff 64
#define Hh 256
#define Cc 10
#define Gg 64

// ---------------- device scratch (static, no allocation) ----------------
__device__ __half g_zh[Nn * Hh];         // prescaled GEMM output: dinv_m * z_m (fp16)
__device__ __half g_hi[Nn * Hh];         // hidden state hi (fp16)
__device__ __half g_lo[Nn * Hh];         // hidden state lo (fp16)
__device__ __half g_xhi[Nn * Ff];        // aggregated X hi
__device__ __half g_xlo[Nn * Ff];        // aggregated X lo
__device__ __half g_whiT[4 * Hh * Hh];   // W2..W5 transposed [m][k], hi
__device__ __half g_wloT[4 * Hh * Hh];   // W2..W5 transposed [m][k], lo
__device__ __half g_w1hiT[Hh * Ff];      // W1 transposed [m=256][k=64]
__device__ __half g_w1loT[Hh * Ff];

__device__ float g_dinv[Nn];
__device__ int   g_cnt[Nn];
__device__ int   g_off[Nn + 1];
__device__ int   g_cur[Nn];
__device__ int   g_csr[Ee];
__device__ float g_pool[Gg * Hh];
__device__ int   g_pcnt[Gg];

// ---------------- init ----------------
__global__ void init_kernel() {
    int idx = blockIdx.x * blockDim.x + threadIdx.x;
    if (idx < Nn) g_cnt[idx] = 0;
    if (idx < Gg * Hh) g_pool[idx] = 0.0f;
    if (idx < Gg) g_pcnt[idx] = 0;
}

// ---------------- degree count (edges) + per-graph node count ----------------
__global__ void deg_kernel(const int* __restrict__ edge_index,
                           const int* __restrict__ batch) {
    int e = blockIdx.x * blockDim.x + threadIdx.x;
    if (e < Ee) {
        atomicAdd(&g_cnt[edge_index[Ee + e]], 1);
    } else if (e < Ee + Nn) {
        atomicAdd(&g_pcnt[batch[e - Ee]], 1);
    }
}

// ---------------- single-block scan ----------------
#define SCAN_T 1024
#define SCAN_CH ((Nn + SCAN_T - 1) / SCAN_T)
__global__ void scan_kernel() {
    __shared__ int sh[SCAN_T];
    int t = threadIdx.x;
    int base = t * SCAN_CH;
    int s = 0;
    #pragma unroll
    for (int i = 0; i < SCAN_CH; i++) {
        int idx = base + i;
        if (idx < Nn) s += g_cnt[idx];
    }
    sh[t] = s;
    __syncthreads();
    for (int d = 1; d < SCAN_T; d <<= 1) {
        int v = (t >= d) ? sh[t - d] : 0;
        __syncthreads();
        sh[t] += v;
        __syncthreads();
    }
    int run = (t == 0) ? 0 : sh[t - 1];
    for (int i = 0; i < SCAN_CH; i++) {
        int idx = base + i;
        if (idx < Nn) {
            int c = g_cnt[idx];
            g_off[idx] = run;
            g_cur[idx] = run;
            g_dinv[idx] = rsqrtf((float)(c + 1));
            run += c;
        }
    }
    if (t == SCAN_T - 1) g_off[Nn] = sh[SCAN_T - 1];
}

// ---------------- scatter into dest-sorted CSR ----------------
__global__ void scatter_kernel(const int* __restrict__ edge_index) {
    int e = blockIdx.x * blockDim.x + threadIdx.x;
    if (e < Ee) {
        int r = edge_index[e];
        int c = edge_index[Ee + e];
        g_csr[atomicAdd(&g_cur[c], 1)] = r;
    }
}

// ---------------- weight prep (all 5 weights in one launch) ----------------
__global__ void wprep_kernel(const float* __restrict__ W1,
                             const float* __restrict__ W2,
                             const float* __restrict__ W3,
                             const float* __restrict__ W4,
                             const float* __restrict__ W5) {
    int idx = blockIdx.x * blockDim.x + threadIdx.x;
    if (idx < Ff * Hh) {
        int m = idx / Ff, k = idx - m * Ff;
        float v = W1[k * Hh + m];
        __half hi = __float2half_rn(v);
        g_w1hiT[idx] = hi;
        g_w1loT[idx] = __float2half_rn(v - __half2float(hi));
        return;
    }
    int r = idx - Ff * Hh;
    if (r >= 4 * Hh * Hh) return;
    int widx = r >> 16;
    int loc = r & 65535;
    int m = loc >> 8, k = loc & 255;
    const float* W = (widx == 0) ? W2 : (widx == 1) ? W3 : (widx == 2) ? W4 : W5;
    float v = W[k * Hh + m];
    __half hi = __float2half_rn(v);
    g_whiT[r] = hi;
    g_wloT[r] = __float2half_rn(v - __half2float(hi));
}

// ---------------- aggregate raw X (F=64), write fp16 hi/lo ----------------
__global__ void aggx_kernel(const float* __restrict__ x) {
    int tid = threadIdx.x;
    int node = blockIdx.x * 16 + (tid >> 4);
    int lane = tid & 15;
    float di = g_dinv[node];
    const float4* x4 = (const float4*)x;
    float4 self = x4[node * 16 + lane];
    float4 acc;
    acc.x = di * self.x; acc.y = di * self.y; acc.z = di * self.z; acc.w = di * self.w;
    int s = g_off[node], e = g_off[node + 1];
    int k = s;
    for (; k + 2 <= e; k += 2) {
        int j0 = g_csr[k], j1 = g_csr[k + 1];
        float w0 = g_dinv[j0], w1 = g_dinv[j1];
        float4 v0 = x4[j0 * 16 + lane];
        float4 v1 = x4[j1 * 16 + lane];
        acc.x = fmaf(w0, v0.x, acc.x); acc.y = fmaf(w0, v0.y, acc.y);
        acc.z = fmaf(w0, v0.z, acc.z); acc.w = fmaf(w0, v0.w, acc.w);
        acc.x = fmaf(w1, v1.x, acc.x); acc.y = fmaf(w1, v1.y, acc.y);
        acc.z = fmaf(w1, v1.z, acc.z); acc.w = fmaf(w1, v1.w, acc.w);
    }
    if (k < e) {
        int j0 = g_csr[k];
        float w0 = g_dinv[j0];
        float4 v0 = x4[j0 * 16 + lane];
        acc.x = fmaf(w0, v0.x, acc.x); acc.y = fmaf(w0, v0.y, acc.y);
        acc.z = fmaf(w0, v0.z, acc.z); acc.w = fmaf(w0, v0.w, acc.w);
    }
    float r0 = di * acc.x, r1 = di * acc.y, r2 = di * acc.z, r3 = di * acc.w;
    __half h0 = __float2half_rn(r0), h1 = __float2half_rn(r1);
    __half h2 = __float2half_rn(r2), h3 = __float2half_rn(r3);
    __half l0 = __float2half_rn(r0 - __half2float(h0));
    __half l1 = __float2half_rn(r1 - __half2float(h1));
    __half l2 = __float2half_rn(r2 - __half2float(h2));
    __half l3 = __float2half_rn(r3 - __half2float(h3));
    int off = node * Ff + lane * 4;
    *(__half2*)(g_xhi + off)     = __halves2half2(h0, h1);
    *(__half2*)(g_xhi + off + 2) = __halves2half2(h2, h3);
    *(__half2*)(g_xlo + off)     = __halves2half2(l0, l1);
    *(__half2*)(g_xlo + off + 2) = __halves2half2(l2, l3);
}

// ---------------- aggregation (layers 2..5): warp-per-node over fp16 zs ----
// zs already prescaled by dinv_j, so: h[i] = relu(dinv_i*(sum_{j in N} zs[j] + zs[i]) + b)
__device__ __forceinline__ void add8(float* acc, uint4 v) {
    const __half2* h = (const __half2*)&v;
    #pragma unroll
    for (int i = 0; i < 4; i++) {
        float2 f = __half22float2(h[i]);
        acc[2 * i]     += f.x;
        acc[2 * i + 1] += f.y;
    }
}

template <bool POOL>
__global__ void agg_kernel(const float* __restrict__ b, const int* __restrict__ batch) {
    int warp = threadIdx.x >> 5;
    int lane = threadIdx.x & 31;
    int node = blockIdx.x * 8 + warp;          // 2500 blocks * 8 nodes
    float di = g_dinv[node];
    const uint4* zrow = (const uint4*)g_zh;    // 32 uint4 per row

    float acc[8];
    {   // self term (zs[i] = dinv_i * z_i)
        uint4 v = zrow[node * 32 + lane];
        const __half2* h = (const __half2*)&v;
        #pragma unroll
        for (int i = 0; i < 4; i++) {
            float2 f = __half22float2(h[i]);
            acc[2 * i] = f.x;
            acc[2 * i + 1] = f.y;
        }
    }
    int s = g_off[node], e = g_off[node + 1];
    int k = s;
    for (; k + 4 <= e; k += 4) {
        int j0 = g_csr[k], j1 = g_csr[k + 1], j2 = g_csr[k + 2], j3 = g_csr[k + 3];
        uint4 v0 = zrow[j0 * 32 + lane];
        uint4 v1 = zrow[j1 * 32 + lane];
        uint4 v2 = zrow[j2 * 32 + lane];
        uint4 v3 = zrow[j3 * 32 + lane];
        add8(acc, v0); add8(acc, v1); add8(acc, v2); add8(acc, v3);
    }
    for (; k < e; k++) {
        uint4 v0 = zrow[g_csr[k] * 32 + lane];
        add8(acc, v0);
    }

    const float4 b0 = ((const float4*)b)[lane * 2];
    const float4 b1 = ((const float4*)b)[lane * 2 + 1];
    float r[8];
    r[0] = fmaxf(fmaf(di, acc[0], b0.x), 0.0f);
    r[1] = fmaxf(fmaf(di, acc[1], b0.y), 0.0f);
    r[2] = fmaxf(fmaf(di, acc[2], b0.z), 0.0f);
    r[3] = fmaxf(fmaf(di, acc[3], b0.w), 0.0f);
    r[4] = fmaxf(fmaf(di, acc[4], b1.x), 0.0f);
    r[5] = fmaxf(fmaf(di, acc[5], b1.y), 0.0f);
    r[6] = fmaxf(fmaf(di, acc[6], b1.z), 0.0f);
    r[7] = fmaxf(fmaf(di, acc[7], b1.w), 0.0f);

    if (POOL) {
        int gph = batch[node];
        float* p = g_pool + gph * Hh + lane * 8;
        #pragma unroll
        for (int i = 0; i < 8; i++) atomicAdd(p + i, r[i]);
    } else {
        uint4 hv, lv;
        __half2* hh = (__half2*)&hv;
        __half2* ll = (__half2*)&lv;
        #pragma unroll
        for (int i = 0; i < 4; i++) {
            __half ha = __float2half_rn(r[2 * i]);
            __half hb = __float2half_rn(r[2 * i + 1]);
            __half la = __float2half_rn(r[2 * i] - __half2float(ha));
            __half lb = __float2half_rn(r[2 * i + 1] - __half2float(hb));
            hh[i] = __halves2half2(ha, hb);
            ll[i] = __halves2half2(la, lb);
        }
        int off = node * Hh + lane * 8;
        *(uint4*)(g_hi + off) = hv;
        *(uint4*)(g_lo + off) = lv;
    }
}

// ---------------- split-fp16 tensor-core GEMM (cp.async double-buffered) ----
#define MMA16816(d, a, b)                                                     \
    asm volatile(                                                             \
        "mma.sync.aligned.m16n8k16.row.col.f32.f16.f16.f32 "                  \
        "{%0,%1,%2,%3},{%4,%5,%6,%7},{%8,%9},{%0,%1,%2,%3};"                  \
        : "+f"(d[0]), "+f"(d[1]), "+f"(d[2]), "+f"(d[3])                      \
        : "r"(a[0]), "r"(a[1]), "r"(a[2]), "r"(a[3]), "r"(b[0]), "r"(b[1]))

__device__ __forceinline__ void cp16(uint32_t dst, const void* src) {
    asm volatile("cp.async.cg.shared.global [%0], [%1], 16;" :: "r"(dst), "l"(src));
}
__device__ __forceinline__ void cp_commit() {
    asm volatile("cp.async.commit_group;");
}
template <int NWait>
__device__ __forceinline__ void cp_wait() {
    asm volatile("cp.async.wait_group %0;" :: "n"(NWait));
}

#define TILE_H 5120
#define BUF_H  (4 * TILE_H)

template <int K, bool RELU>
__global__ __launch_bounds__(256, 2) void gemm_kernel(int widx, const float* __restrict__ bias) {
    const __half* __restrict__ Ahi = (K == Ff) ? g_xhi : g_hi;
    const __half* __restrict__ Alo = (K == Ff) ? g_xlo : g_lo;
    const __half* __restrict__ Bhi = (K == Ff) ? g_w1hiT : g_whiT + widx * (Hh * Hh);
    const __half* __restrict__ Blo = (K == Ff) ? g_w1loT : g_wloT + widx * (Hh * Hh);

    extern __shared__ __half sh[];
    const uint32_t sh32 = (uint32_t)__cvta_generic_to_shared(sh);

    const int tid = threadIdx.x;
    const int warp = tid >> 5;
    const int lane = tid & 31;
    const int g = lane >> 2;
    const int t = lane & 3;
    const int wm = warp >> 2;
    const int wn = warp & 3;
    const int rowbase = blockIdx.y * 128;
    const int colbase = blockIdx.x * 128;

    const int lrow = tid >> 1;
    const int lch = tid & 1;
    int arow = rowbase + lrow;
    if (arow > Nn - 1) arow = Nn - 1;
    const __half* pAhi = Ahi + arow * K + lch * 16;
    const __half* pAlo = Alo + arow * K + lch * 16;
    const __half* pBhi = Bhi + (colbase + lrow) * K + lch * 16;
    const __half* pBlo = Blo + (colbase + lrow) * K + lch * 16;
    const uint32_t sidx_b = (uint32_t)(lrow * 40 + lch * 16) * 2;

    float acc[4][4][4];
    #pragma unroll
    for (int a = 0; a < 4; a++)
        #pragma unroll
        for (int bq = 0; bq < 4; bq++)
            #pragma unroll
            for (int c = 0; c < 4; c++) acc[a][bq][c] = 0.0f;

    const int NT = K / 32;

    auto issue = [&](int kt, int buf) {
        int k0 = kt * 32;
        uint32_t base = sh32 + (uint32_t)buf * (BUF_H * 2) + sidx_b;
        cp16(base,                     pAhi + k0);
        cp16(base + 16,                pAhi + k0 + 8);
        cp16(base + TILE_H * 2,        pAlo + k0);
        cp16(base + TILE_H * 2 + 16,   pAlo + k0 + 8);
        cp16(base + TILE_H * 4,        pBhi + k0);
        cp16(base + TILE_H * 4 + 16,   pBhi + k0 + 8);
        cp16(base + TILE_H * 6,        pBlo + k0);
        cp16(base + TILE_H * 6 + 16,   pBlo + k0 + 8);
    };

    issue(0, 0);
    cp_commit();

    #pragma unroll 1
    for (int kt = 0; kt < NT; kt++) {
        int buf = kt & 1;
        if (kt + 1 < NT) {
            issue(kt + 1, buf ^ 1);
            cp_commit();
            cp_wait<1>();
        } else {
            cp_wait<0>();
        }
        __syncthreads();

        const __half* sAhi = sh + buf * BUF_H;
        const __half* sAlo = sAhi + TILE_H;
        const __half* sBhi = sAhi + 2 * TILE_H;
        const __half* sBlo = sAhi + 3 * TILE_H;

        #pragma unroll
        for (int kh = 0; kh < 32; kh += 16) {
            uint32_t Ah[4][4], Al[4][4], Bh[4][2], Bl[4][2];
            #pragma unroll
            for (int im = 0; im < 4; im++) {
                int mb = (wm * 64 + im * 16 + g) * 40 + kh + 2 * t;
                Ah[im][0] = *(const uint32_t*)&sAhi[mb];
                Ah[im][1] = *(const uint32_t*)&sAhi[mb + 8 * 40];
                Ah[im][2] = *(const uint32_t*)&sAhi[mb + 8];
                Ah[im][3] = *(const uint32_t*)&sAhi[mb + 8 * 40 + 8];
                Al[im][0] = *(const uint32_t*)&sAlo[mb];
                Al[im][1] = *(const uint32_t*)&sAlo[mb + 8 * 40];
                Al[im][2] = *(const uint32_t*)&sAlo[mb + 8];
                Al[im][3] = *(const uint32_t*)&sAlo[mb + 8 * 40 + 8];
            }
            #pragma unroll
            for (int in = 0; in < 4; in++) {
                int nb = (wn * 32 + in * 8 + g) * 40 + kh + 2 * t;
                Bh[in][0] = *(const uint32_t*)&sBhi[nb];
                Bh[in][1] = *(const uint32_t*)&sBhi[nb + 8];
                Bl[in][0] = *(const uint32_t*)&sBlo[nb];
                Bl[in][1] = *(const uint32_t*)&sBlo[nb + 8];
            }
            #pragma unroll
            for (int im = 0; im < 4; im++)
                #pragma unroll
                for (int in = 0; in < 4; in++) {
                    MMA16816(acc[im][in], Ah[im], Bh[in]);
                    MMA16816(acc[im][in], Al[im], Bh[in]);
                    MMA16816(acc[im][in], Ah[im], Bl[in]);
                }
        }
        __syncthreads();
    }

    // epilogue
    #pragma unroll
    for (int im = 0; im < 4; im++) {
        int m0 = rowbase + wm * 64 + im * 16 + g;
        float dm0 = (m0 < Nn) ? g_dinv[m0] : 0.0f;
        float dm1 = (m0 + 8 < Nn) ? g_dinv[m0 + 8] : 0.0f;
        #pragma unroll
        for (int in = 0; in < 4; in++) {
            int n = colbase + wn * 32 + in * 8 + 2 * t;
            float c0 = acc[im][in][0], c1 = acc[im][in][1];
            float c2 = acc[im][in][2], c3 = acc[im][in][3];
            if (RELU) {
                float bb0 = bias[n], bb1 = bias[n + 1];
                if (m0 < Nn) {
                    float r0 = fmaxf(c0 + bb0, 0.0f), r1 = fmaxf(c1 + bb1, 0.0f);
                    __half h0 = __float2half_rn(r0), h1 = __float2half_rn(r1);
                    __half l0 = __float2half_rn(r0 - __half2float(h0));
                    __half l1 = __float2half_rn(r1 - __half2float(h1));
                    *(__half2*)(g_hi + m0 * Hh + n) = __halves2half2(h0, h1);
                    *(__half2*)(g_lo + m0 * Hh + n) = __halves2half2(l0, l1);
                }
                if (m0 + 8 < Nn) {
                    float r2 = fmaxf(c2 + bb0, 0.0f), r3 = fmaxf(c3 + bb1, 0.0f);
                    __half h2 = __float2half_rn(r2), h3 = __float2half_rn(r3);
                    __half l2 = __float2half_rn(r2 - __half2float(h2));
                    __half l3 = __float2half_rn(r3 - __half2float(h3));
                    *(__half2*)(g_hi + (m0 + 8) * Hh + n) = __halves2half2(h2, h3);
                    *(__half2*)(g_lo + (m0 + 8) * Hh + n) = __halves2half2(l2, l3);
                }
            } else {
                // write prescaled fp16: zs[m] = dinv[m] * z[m]
                if (m0 < Nn)
                    *(__half2*)(g_zh + m0 * Hh + n) = __floats2half2_rn(dm0 * c0, dm0 * c1);
                if (m0 + 8 < Nn)
                    *(__half2*)(g_zh + (m0 + 8) * Hh + n) = __floats2half2_rn(dm1 * c2, dm1 * c3);
            }
        }
    }
}

// ---------------- output head ----------------
__global__ void out_kernel(const float* __restrict__ Wout,
                           const float* __restrict__ bout,
                           float* __restrict__ out) {
    __shared__ float sh[Hh];
    int g = blockIdx.x;
    int f = threadIdx.x;
    int c = g_pcnt[g];
    float inv = 1.0f / fmaxf((float)c, 1.0f);
    sh[f] = g_pool[g * Hh + f] * inv;
    __syncthreads();
    if (f < Cc) {
        float a = bout[f];
        for (int k = 0; k < Hh; k++)
            a = fmaf(sh[k], Wout[k * Cc + f], a);
        out[g * Cc + f] = a;
    }
}

// ---------------- launch ----------------
extern "C" void kernel_launch(void* const* d_in, const int* in_sizes, int n_in,
                              void* d_out, int out_size) {
    const float* x     = (const float*)d_in[0];
    const int*   ei    = (const int*)d_in[1];
    const int*   batch = (const int*)d_in[2];
    const float* W1 = (const float*)d_in[3];
    const float* b1 = (const float*)d_in[4];
    const float* W2 = (const float*)d_in[5];
    const float* b2 = (const float*)d_in[6];
    const float* W3 = (const float*)d_in[7];
    const float* b3 = (const float*)d_in[8];
    const float* W4 = (const float*)d_in[9];
    const float* b4 = (const float*)d_in[10];
    const float* W5 = (const float*)d_in[11];
    const float* b5 = (const float*)d_in[12];
    const float* Wout = (const float*)d_in[13];
    const float* bout = (const float*)d_in[14];
    float* out = (float*)d_out;

    const int SMEM_BYTES = 2 * BUF_H * 2;   // 81920
    static bool attr_set = false;
    if (!attr_set) {
        cudaFuncSetAttribute(gemm_kernel<Ff, true>,
                             cudaFuncAttributeMaxDynamicSharedMemorySize, SMEM_BYTES);
        cudaFuncSetAttribute(gemm_kernel<Hh, false>,
                             cudaFuncAttributeMaxDynamicSharedMemorySize, SMEM_BYTES);
        attr_set = true;
    }

    int eblocks = (Ee + 255) / 256;
    int dblocks = (Ee + Nn + 255) / 256;
    dim3 ggrid(Hh / 128, (Nn + 127) / 128);   // (2, 157)

    init_kernel<<<(Nn + 255) / 256, 256>>>();
    deg_kernel<<<dblocks, 256>>>(ei, batch);
    scan_kernel<<<1, SCAN_T>>>();
    scatter_kernel<<<eblocks, 256>>>(ei);
    wprep_kernel<<<(Ff * Hh + 4 * Hh * Hh + 255) / 256, 256>>>(W1, W2, W3, W4, W5);

    // layer 1: aggregate x first (A(XW) = (AX)W), then GEMM with bias+relu
    aggx_kernel<<<Nn / 16, 256>>>(x);
    gemm_kernel<Ff, true><<<ggrid, 256, SMEM_BYTES>>>(0, b1);

    // layers 2..5
    gemm_kernel<Hh, false><<<ggrid, 256, SMEM_BYTES>>>(0, nullptr);
    agg_kernel<false><<<Nn / 8, 256>>>(b2, batch);
    gemm_kernel<Hh, false><<<ggrid, 256, SMEM_BYTES>>>(1, nullptr);
    agg_kernel<false><<<Nn / 8, 256>>>(b3, batch);
    gemm_kernel<Hh, false><<<ggrid, 256, SMEM_BYTES>>>(2, nullptr);
    agg_kernel<false><<<Nn / 8, 256>>>(b4, batch);
    gemm_kernel<Hh, false><<<ggrid, 256, SMEM_BYTES>>>(3, nullptr);
    agg_kernel<true><<<Nn / 8, 256>>>(b5, batch);   // fused pool

    out_kernel<<<Gg, 256>>>(Wout, bout, out);
}